// round 4
// baseline (speedup 1.0000x reference)
#include <cuda_runtime.h>
#include <cuda_fp16.h>
#include <cstdint>

// ============================================================================
// out[b,s,o] = sum_k x[b,s,k] * (centroids[nib(o,k)] * scales[o,k/64])
// B=4 S=2048 K=4096 O=4096.
//
// Base-ISA tensor path (harness targets sm_103 PTX; tcgen05 unavailable):
// cp.async + ldmatrix + mma.sync.m16n8k16 (fp16 in, fp32 accum).
//
// Numerics: A' = [xh, xl] fp16 pair interleaved along K, B' = [w~, w~]
// duplicated fp16 -> A'.B' = x * fp16(w); only error is w's fp16 rounding
// (~1.4e-4 rel << 1e-3).
//
// R4: inputs identified by element count; weight_packed dtype (uint8-packed
// vs int32-expanded bytes) auto-detected on device.
// ============================================================================

static constexpr int KDIM = 4096, ODIM = 4096;
static constexpr int MDIM = 8192;          // 4*2048
static constexpr int K2   = 2 * KDIM;      // 8192

static constexpr int TM = 128, TN = 128, TK = 64;
static constexpr int NCHUNK = K2 / TK;     // 128
static constexpr int STAGES = 3;
static constexpr int STAGE_BYTES = (TM + TN) * TK * 2;   // 32768
static constexpr int SMEM_BYTES  = STAGES * STAGE_BYTES; // 98304

__device__ __half g_A[(size_t)MDIM * K2];   // 128 MiB
__device__ __half g_B[(size_t)ODIM * K2];   //  64 MiB
__device__ int    g_wfmt;                   // 1 = int32-expanded bytes

// ---------------------------------------------------------------------------
__device__ __forceinline__ uint32_t smem_u32(const void* p) {
    uint32_t a;
    asm("{ .reg .u64 t; cvta.to.shared.u64 t, %1; cvt.u32.u64 %0, t; }"
        : "=r"(a) : "l"(p));
    return a;
}

__device__ __forceinline__ void cp_async16(uint32_t dst, const void* src) {
    asm volatile("cp.async.cg.shared.global [%0], [%1], 16;"
                 :: "r"(dst), "l"(src) : "memory");
}
__device__ __forceinline__ void cp_commit() {
    asm volatile("cp.async.commit_group;" ::: "memory");
}
template <int N>
__device__ __forceinline__ void cp_wait() {
    asm volatile("cp.async.wait_group %0;" :: "n"(N) : "memory");
}

__device__ __forceinline__ void ldsm_x4(uint32_t* r, uint32_t addr) {
    asm volatile("ldmatrix.sync.aligned.m8n8.x4.shared.b16 {%0,%1,%2,%3}, [%4];"
                 : "=r"(r[0]), "=r"(r[1]), "=r"(r[2]), "=r"(r[3]) : "r"(addr));
}

__device__ __forceinline__ void mma16816(float* c, const uint32_t* a, const uint32_t* b) {
    asm volatile(
        "mma.sync.aligned.m16n8k16.row.col.f32.f16.f16.f32 "
        "{%0,%1,%2,%3}, {%4,%5,%6,%7}, {%8,%9}, {%0,%1,%2,%3};"
        : "+f"(c[0]), "+f"(c[1]), "+f"(c[2]), "+f"(c[3])
        : "r"(a[0]), "r"(a[1]), "r"(a[2]), "r"(a[3]), "r"(b[0]), "r"(b[1]));
}

// swizzled byte offset within a [rows][64] fp16 tile (128B rows)
__device__ __forceinline__ uint32_t swz(int r, int kb) {
    return (uint32_t)(r * 128 + (kb ^ ((r & 7) << 4)));
}

// ---------------------------------------------------------------------------
// Prep kernels
// ---------------------------------------------------------------------------
__global__ void k_split_x(const float4* __restrict__ x) {
    size_t i = (size_t)blockIdx.x * blockDim.x + threadIdx.x;   // float4s
    float4 v = x[i];
    union { __half h[8]; uint4 u; } o;
    float f[4] = {v.x, v.y, v.z, v.w};
    #pragma unroll
    for (int j = 0; j < 4; j++) {
        __half hi = __float2half(f[j]);
        o.h[2*j]   = hi;
        o.h[2*j+1] = __float2half(f[j] - __half2float(hi));
    }
    *reinterpret_cast<uint4*>(g_A + i * 8) = o.u;
}

// detect weight_packed storage format: uint8-packed words vs int32-expanded
__global__ void k_detect(const uint32_t* __restrict__ wp) {
    if (blockIdx.x == 0 && threadIdx.x == 0) {
        int expanded = 1;
        #pragma unroll 1
        for (int i = 0; i < 64; i++)
            if (wp[i] & 0xFFFFFF00u) { expanded = 0; break; }
        g_wfmt = expanded;
    }
}

// one thread <-> 8 logical packed bytes = 16 weights = 32 output halfs
__global__ void k_dequant(const uint32_t* __restrict__ wp,
                          const float* __restrict__ cent,
                          const float* __restrict__ scales) {
    __shared__ float sc[16];
    if (threadIdx.x < 16) sc[threadIdx.x] = cent[threadIdx.x];
    __syncthreads();

    const int t  = blockIdx.x * blockDim.x + threadIdx.x;  // 8-byte group idx
    const int o  = t >> 8;             // 256 groups per output row (2048 B/row)
    const int jb = (t & 255) * 8;      // byte offset within row
    const float s = __ldg(scales + o * 64 + (jb >> 5));    // 32 bytes per block

    uint32_t w[2];
    if (g_wfmt) {                      // int32-expanded: one byte per int32
        const int32_t* wi = reinterpret_cast<const int32_t*>(wp);
        const size_t j0 = (size_t)t * 8;
        w[0] = w[1] = 0;
        #pragma unroll
        for (int i = 0; i < 4; i++) {
            w[0] |= ((uint32_t)wi[j0 + i]     & 0xFFu) << (8 * i);
            w[1] |= ((uint32_t)wi[j0 + 4 + i] & 0xFFu) << (8 * i);
        }
    } else {                           // true uint8 packing: read as words
        w[0] = wp[t * 2];
        w[1] = wp[t * 2 + 1];
    }

    union { __half h[32]; uint4 u[4]; } out;
    #pragma unroll
    for (int half = 0; half < 2; half++) {
        const uint32_t word = w[half];
        #pragma unroll
        for (int b = 0; b < 4; b++) {
            const uint32_t byte = (word >> (8 * b)) & 0xFF;
            const __half w0 = __float2half(sc[byte >> 4] * s);   // HIGH nibble first
            const __half w1 = __float2half(sc[byte & 15] * s);
            const int base = half * 16 + 4 * b;
            out.h[base + 0] = w0; out.h[base + 1] = w0;          // duplicated pair
            out.h[base + 2] = w1; out.h[base + 3] = w1;
        }
    }
    uint4* dst = reinterpret_cast<uint4*>(g_B + (size_t)o * K2 + (size_t)jb * 4);
    #pragma unroll
    for (int i = 0; i < 4; i++) dst[i] = out.u[i];
}

// ---------------------------------------------------------------------------
// GEMM: out[8192,4096] = A'[8192,8192] @ B'[4096,8192]^T  (fp16 in, fp32 acc)
// ---------------------------------------------------------------------------
__global__ void __launch_bounds__(256, 2) k_gemm(float* __restrict__ out) {
    extern __shared__ char smem[];
    const uint32_t sbase = smem_u32(smem);

    const int tid  = threadIdx.x;
    const int wid  = tid >> 5;
    const int lane = tid & 31;
    const int m0   = blockIdx.y * TM;
    const int n0   = blockIdx.x * TN;

    const int wm0 = (wid >> 2) * 64;    // warp m offset
    const int wn0 = (wid & 3) * 32;     // warp n offset

    float acc[4][4][4];
    #pragma unroll
    for (int i = 0; i < 4; i++)
        #pragma unroll
        for (int j = 0; j < 4; j++)
            #pragma unroll
            for (int k = 0; k < 4; k++) acc[i][j][k] = 0.f;

    auto issue_chunk = [&](int kc, int stage) {
        const uint32_t aS = sbase + stage * STAGE_BYTES;
        const uint32_t bS = aS + TM * 128;
        const size_t kofs = (size_t)kc * TK;
        #pragma unroll
        for (int it = 0; it < 8; it++) {
            const int v = tid + it * 256;
            if (it < 4) {
                const int r = v >> 3, c = v & 7;
                cp_async16(aS + swz(r, c * 16),
                           g_A + (size_t)(m0 + r) * K2 + kofs + c * 8);
            } else {
                const int t = v - 1024;
                const int r = t >> 3, c = t & 7;
                cp_async16(bS + swz(r, c * 16),
                           g_B + (size_t)(n0 + r) * K2 + kofs + c * 8);
            }
        }
        cp_commit();
    };

    issue_chunk(0, 0);
    issue_chunk(1, 1);

    const int laneA_r  = lane & 15;
    const int laneA_kb = (lane >> 4) << 4;
    const int laneB_r  = ((lane & 16) >> 1) + (lane & 7);
    const int laneB_kb = ((lane >> 3) & 1) << 4;

    for (int kc = 0; kc < NCHUNK; kc++) {
        const int stage = kc % STAGES;

        __syncthreads();
        if (kc + 2 < NCHUNK) issue_chunk(kc + 2, (kc + 2) % STAGES);
        else cp_commit();
        cp_wait<2>();
        __syncthreads();

        const uint32_t aS = sbase + stage * STAGE_BYTES;
        const uint32_t bS = aS + TM * 128;

        #pragma unroll
        for (int ks = 0; ks < 4; ks++) {
            const int kb = ks * 32;
            uint32_t a[4][4];
            #pragma unroll
            for (int tm = 0; tm < 4; tm++) {
                const int r = wm0 + tm * 16 + laneA_r;
                ldsm_x4(a[tm], aS + swz(r, kb + laneA_kb));
            }
            uint32_t b[4][2];
            #pragma unroll
            for (int j = 0; j < 2; j++) {
                const int r = wn0 + j * 16 + laneB_r;
                uint32_t t[4];
                ldsm_x4(t, bS + swz(r, kb + laneB_kb));
                b[2*j][0] = t[0];   b[2*j][1] = t[1];
                b[2*j+1][0] = t[2]; b[2*j+1][1] = t[3];
            }
            #pragma unroll
            for (int tm = 0; tm < 4; tm++)
                #pragma unroll
                for (int tn = 0; tn < 4; tn++)
                    mma16816(acc[tm][tn], a[tm], b[tn]);
        }
    }

    const int mrow = lane >> 2;
    const int ncol = (lane & 3) * 2;
    #pragma unroll
    for (int tm = 0; tm < 4; tm++) {
        #pragma unroll
        for (int tn = 0; tn < 4; tn++) {
            const int m = m0 + wm0 + tm * 16 + mrow;
            const int n = n0 + wn0 + tn * 8 + ncol;
            float2* p0 = reinterpret_cast<float2*>(out + (size_t)m * ODIM + n);
            float2* p1 = reinterpret_cast<float2*>(out + (size_t)(m + 8) * ODIM + n);
            *p0 = make_float2(acc[tm][tn][0], acc[tm][tn][1]);
            *p1 = make_float2(acc[tm][tn][2], acc[tm][tn][3]);
        }
    }
}

// ---------------------------------------------------------------------------
extern "C" void kernel_launch(void* const* d_in, const int* in_sizes, int n_in,
                              void* d_out, int out_size) {
    (void)out_size;
    const float*    x      = nullptr;
    const uint32_t* wp     = nullptr;
    const float*    cent   = nullptr;
    const float*    scales = nullptr;

    for (int i = 0; i < n_in; i++) {
        switch (in_sizes[i]) {
            case 16:        cent   = (const float*)d_in[i];    break;
            case 262144:    scales = (const float*)d_in[i];    break;
            case 33554432:  x      = (const float*)d_in[i];    break;
            default:        wp     = (const uint32_t*)d_in[i]; break;  // 8388608
        }
    }
    float* outp = (float*)d_out;

    k_detect<<<1, 32>>>(wp);
    k_split_x<<<32768, 256>>>(reinterpret_cast<const float4*>(x));
    k_dequant<<<4096, 256>>>(wp, cent, scales);   // 1,048,576 threads

    cudaFuncSetAttribute(k_gemm, cudaFuncAttributeMaxDynamicSharedMemorySize, SMEM_BYTES);
    k_gemm<<<dim3(ODIM / TN, MDIM / TM), 256, SMEM_BYTES>>>(outp);
}

// round 6
// speedup vs baseline: 1.9030x; 1.9030x over previous
#include <cuda_runtime.h>
#include <cuda_fp16.h>
#include <cstdint>

// ============================================================================
// out[b,s,o] = sum_k x[b,s,k] * (centroids[nib(o,k)] * scales[o,k/64])
// B=4 S=2048 K=4096 O=4096.
//
// Base-ISA tensor path (harness targets sm_103 PTX; tcgen05 unavailable):
// cp.async + ldmatrix + mma.sync.m16n8k16 (fp16 in, fp32 accum).
//
// R5: plain fp16 GEMM at K=4096 (no hi/lo split). Error = x-rounding (+2e-4)
// quad-summed with w-rounding (2.08e-4 measured) -> ~2.9e-4 << 1e-3, at HALF
// the tensor work of R4 (which measured tensor-pipe-bound at 73.4%).
// ============================================================================

static constexpr int KDIM = 4096, ODIM = 4096;
static constexpr int MDIM = 8192;          // 4*2048

static constexpr int TM = 128, TN = 128, TK = 64;
static constexpr int NCHUNK = KDIM / TK;   // 64
static constexpr int STAGES = 3;
static constexpr int STAGE_BYTES = (TM + TN) * TK * 2;   // 32768
static constexpr int SMEM_BYTES  = STAGES * STAGE_BYTES; // 98304

__device__ __half g_A[(size_t)MDIM * KDIM];   // 64 MiB
__device__ __half g_B[(size_t)ODIM * KDIM];   // 32 MiB
__device__ int    g_wfmt;                     // 1 = int32-expanded bytes

// ---------------------------------------------------------------------------
__device__ __forceinline__ uint32_t smem_u32(const void* p) {
    uint32_t a;
    asm("{ .reg .u64 t; cvta.to.shared.u64 t, %1; cvt.u32.u64 %0, t; }"
        : "=r"(a) : "l"(p));
    return a;
}

__device__ __forceinline__ void cp_async16(uint32_t dst, const void* src) {
    asm volatile("cp.async.cg.shared.global [%0], [%1], 16;"
                 :: "r"(dst), "l"(src) : "memory");
}
__device__ __forceinline__ void cp_commit() {
    asm volatile("cp.async.commit_group;" ::: "memory");
}
template <int N>
__device__ __forceinline__ void cp_wait() {
    asm volatile("cp.async.wait_group %0;" :: "n"(N) : "memory");
}

__device__ __forceinline__ void ldsm_x4(uint32_t* r, uint32_t addr) {
    asm volatile("ldmatrix.sync.aligned.m8n8.x4.shared.b16 {%0,%1,%2,%3}, [%4];"
                 : "=r"(r[0]), "=r"(r[1]), "=r"(r[2]), "=r"(r[3]) : "r"(addr));
}

__device__ __forceinline__ void mma16816(float* c, const uint32_t* a, const uint32_t* b) {
    asm volatile(
        "mma.sync.aligned.m16n8k16.row.col.f32.f16.f16.f32 "
        "{%0,%1,%2,%3}, {%4,%5,%6,%7}, {%8,%9}, {%0,%1,%2,%3};"
        : "+f"(c[0]), "+f"(c[1]), "+f"(c[2]), "+f"(c[3])
        : "r"(a[0]), "r"(a[1]), "r"(a[2]), "r"(a[3]), "r"(b[0]), "r"(b[1]));
}

// swizzled byte offset within a [rows][64] fp16 tile (128B rows)
__device__ __forceinline__ uint32_t swz(int r, int kb) {
    return (uint32_t)(r * 128 + (kb ^ ((r & 7) << 4)));
}

// ---------------------------------------------------------------------------
// Prep kernels
// ---------------------------------------------------------------------------
__global__ void k_convert_x(const float4* __restrict__ x) {
    size_t i = (size_t)blockIdx.x * blockDim.x + threadIdx.x;   // float4s
    float4 v = x[i];
    union { __half2 h2[2]; uint2 u; } o;
    o.h2[0] = __float22half2_rn(make_float2(v.x, v.y));
    o.h2[1] = __float22half2_rn(make_float2(v.z, v.w));
    *reinterpret_cast<uint2*>(g_A + i * 4) = o.u;
}

// detect weight_packed storage: uint8-packed words vs int32-expanded bytes
__global__ void k_detect(const uint32_t* __restrict__ wp) {
    if (blockIdx.x == 0 && threadIdx.x == 0) {
        int expanded = 1;
        #pragma unroll 1
        for (int i = 0; i < 64; i++)
            if (wp[i] & 0xFFFFFF00u) { expanded = 0; break; }
        g_wfmt = expanded;
    }
}

// one thread <-> 8 logical packed bytes = 16 weights = 16 output halfs
__global__ void k_dequant(const uint32_t* __restrict__ wp,
                          const float* __restrict__ cent,
                          const float* __restrict__ scales) {
    __shared__ float sc[16];
    if (threadIdx.x < 16) sc[threadIdx.x] = cent[threadIdx.x];
    __syncthreads();

    const int t  = blockIdx.x * blockDim.x + threadIdx.x;  // 8-byte group idx
    const int o  = t >> 8;             // 256 groups per output row (2048 B/row)
    const int jb = (t & 255) * 8;      // byte offset within row
    const float s = __ldg(scales + o * 64 + (jb >> 5));    // 32 bytes per block

    uint32_t w[2];
    if (g_wfmt) {                      // int32-expanded: one byte per int32
        const int32_t* wi = reinterpret_cast<const int32_t*>(wp);
        const size_t j0 = (size_t)t * 8;
        w[0] = w[1] = 0;
        #pragma unroll
        for (int i = 0; i < 4; i++) {
            w[0] |= ((uint32_t)wi[j0 + i]     & 0xFFu) << (8 * i);
            w[1] |= ((uint32_t)wi[j0 + 4 + i] & 0xFFu) << (8 * i);
        }
    } else {                           // true uint8 packing: read as words
        w[0] = wp[t * 2];
        w[1] = wp[t * 2 + 1];
    }

    union { __half h[16]; uint4 u[2]; } out;
    #pragma unroll
    for (int half = 0; half < 2; half++) {
        const uint32_t word = w[half];
        #pragma unroll
        for (int b = 0; b < 4; b++) {
            const uint32_t byte = (word >> (8 * b)) & 0xFF;
            const int base = half * 8 + 2 * b;
            out.h[base + 0] = __float2half(sc[byte >> 4] * s);   // HIGH nibble first
            out.h[base + 1] = __float2half(sc[byte & 15] * s);
        }
    }
    uint4* dst = reinterpret_cast<uint4*>(g_B + (size_t)o * KDIM + (size_t)jb * 2);
    dst[0] = out.u[0];
    dst[1] = out.u[1];
}

// ---------------------------------------------------------------------------
// GEMM: out[8192,4096] = A[8192,4096] @ B[4096,4096]^T  (fp16 in, fp32 acc)
// ---------------------------------------------------------------------------
__global__ void __launch_bounds__(256, 2) k_gemm(float* __restrict__ out) {
    extern __shared__ char smem[];
    const uint32_t sbase = smem_u32(smem);

    const int tid  = threadIdx.x;
    const int wid  = tid >> 5;
    const int lane = tid & 31;
    const int m0   = blockIdx.y * TM;
    const int n0   = blockIdx.x * TN;

    const int wm0 = (wid >> 2) * 64;    // warp m offset
    const int wn0 = (wid & 3) * 32;     // warp n offset

    float acc[4][4][4];
    #pragma unroll
    for (int i = 0; i < 4; i++)
        #pragma unroll
        for (int j = 0; j < 4; j++)
            #pragma unroll
            for (int k = 0; k < 4; k++) acc[i][j][k] = 0.f;

    auto issue_chunk = [&](int kc, int stage) {
        const uint32_t aS = sbase + stage * STAGE_BYTES;
        const uint32_t bS = aS + TM * 128;
        const size_t kofs = (size_t)kc * TK;
        #pragma unroll
        for (int it = 0; it < 8; it++) {
            const int v = tid + it * 256;
            if (it < 4) {
                const int r = v >> 3, c = v & 7;
                cp_async16(aS + swz(r, c * 16),
                           g_A + (size_t)(m0 + r) * KDIM + kofs + c * 8);
            } else {
                const int t = v - 1024;
                const int r = t >> 3, c = t & 7;
                cp_async16(bS + swz(r, c * 16),
                           g_B + (size_t)(n0 + r) * KDIM + kofs + c * 8);
            }
        }
        cp_commit();
    };

    issue_chunk(0, 0);
    issue_chunk(1, 1);

    const int laneA_r  = lane & 15;
    const int laneA_kb = (lane >> 4) << 4;
    const int laneB_r  = ((lane & 16) >> 1) + (lane & 7);
    const int laneB_kb = ((lane >> 3) & 1) << 4;

    for (int kc = 0; kc < NCHUNK; kc++) {
        const int stage = kc % STAGES;

        __syncthreads();
        if (kc + 2 < NCHUNK) issue_chunk(kc + 2, (kc + 2) % STAGES);
        else cp_commit();
        cp_wait<2>();
        __syncthreads();

        const uint32_t aS = sbase + stage * STAGE_BYTES;
        const uint32_t bS = aS + TM * 128;

        #pragma unroll
        for (int ks = 0; ks < 4; ks++) {
            const int kb = ks * 32;
            uint32_t a[4][4];
            #pragma unroll
            for (int tm = 0; tm < 4; tm++) {
                const int r = wm0 + tm * 16 + laneA_r;
                ldsm_x4(a[tm], aS + swz(r, kb + laneA_kb));
            }
            uint32_t b[4][2];
            #pragma unroll
            for (int j = 0; j < 2; j++) {
                const int r = wn0 + j * 16 + laneB_r;
                uint32_t t[4];
                ldsm_x4(t, bS + swz(r, kb + laneB_kb));
                b[2*j][0] = t[0];   b[2*j][1] = t[1];
                b[2*j+1][0] = t[2]; b[2*j+1][1] = t[3];
            }
            #pragma unroll
            for (int tm = 0; tm < 4; tm++)
                #pragma unroll
                for (int tn = 0; tn < 4; tn++)
                    mma16816(acc[tm][tn], a[tm], b[tn]);
        }
    }

    const int mrow = lane >> 2;
    const int ncol = (lane & 3) * 2;
    #pragma unroll
    for (int tm = 0; tm < 4; tm++) {
        #pragma unroll
        for (int tn = 0; tn < 4; tn++) {
            const int m = m0 + wm0 + tm * 16 + mrow;
            const int n = n0 + wn0 + tn * 8 + ncol;
            float2* p0 = reinterpret_cast<float2*>(out + (size_t)m * ODIM + n);
            float2* p1 = reinterpret_cast<float2*>(out + (size_t)(m + 8) * ODIM + n);
            *p0 = make_float2(acc[tm][tn][0], acc[tm][tn][1]);
            *p1 = make_float2(acc[tm][tn][2], acc[tm][tn][3]);
        }
    }
}

// ---------------------------------------------------------------------------
extern "C" void kernel_launch(void* const* d_in, const int* in_sizes, int n_in,
                              void* d_out, int out_size) {
    (void)out_size;
    const float*    x      = nullptr;
    const uint32_t* wp     = nullptr;
    const float*    cent   = nullptr;
    const float*    scales = nullptr;

    for (int i = 0; i < n_in; i++) {
        switch (in_sizes[i]) {
            case 16:        cent   = (const float*)d_in[i];    break;
            case 262144:    scales = (const float*)d_in[i];    break;
            case 33554432:  x      = (const float*)d_in[i];    break;
            default:        wp     = (const uint32_t*)d_in[i]; break;  // 8388608
        }
    }
    float* outp = (float*)d_out;

    k_detect<<<1, 32>>>(wp);
    k_convert_x<<<32768, 256>>>(reinterpret_cast<const float4*>(x));
    k_dequant<<<4096, 256>>>(wp, cent, scales);   // 1,048,576 threads

    cudaFuncSetAttribute(k_gemm, cudaFuncAttributeMaxDynamicSharedMemorySize, SMEM_BYTES);
    k_gemm<<<dim3(ODIM / TN, MDIM / TM), 256, SMEM_BYTES>>>(outp);
}

// round 7
// speedup vs baseline: 1.9567x; 1.0282x over previous
#include <cuda_runtime.h>
#include <cuda_fp16.h>
#include <cstdint>

// ============================================================================
// out[b,s,o] = sum_k x[b,s,k] * (centroids[nib(o,k)] * scales[o,k/64])
// B=4 S=2048 K=4096 O=4096.
//
// Base-ISA tensor path (harness targets sm_103 PTX; tcgen05 unavailable):
// cp.async + ldmatrix + mma.sync.m16n8k16 (fp16 in, fp32 accum).
//
// R7: single __syncthreads per K-chunk (canonical multistage order:
// wait -> sync -> issue(kc+2) -> compute(kc)). Stage (kc+2)%3 == (kc-1)%3 is
// finished by all warps before the barrier, so the post-sync issue is safe.
// ============================================================================

static constexpr int KDIM = 4096, ODIM = 4096;
static constexpr int MDIM = 8192;          // 4*2048

static constexpr int TM = 128, TN = 128, TK = 64;
static constexpr int NCHUNK = KDIM / TK;   // 64
static constexpr int STAGES = 3;
static constexpr int STAGE_BYTES = (TM + TN) * TK * 2;   // 32768
static constexpr int SMEM_BYTES  = STAGES * STAGE_BYTES; // 98304

__device__ __half g_A[(size_t)MDIM * KDIM];   // 64 MiB
__device__ __half g_B[(size_t)ODIM * KDIM];   // 32 MiB
__device__ int    g_wfmt;                     // 1 = int32-expanded bytes

// ---------------------------------------------------------------------------
__device__ __forceinline__ uint32_t smem_u32(const void* p) {
    uint32_t a;
    asm("{ .reg .u64 t; cvta.to.shared.u64 t, %1; cvt.u32.u64 %0, t; }"
        : "=r"(a) : "l"(p));
    return a;
}

__device__ __forceinline__ void cp_async16(uint32_t dst, const void* src) {
    asm volatile("cp.async.cg.shared.global [%0], [%1], 16;"
                 :: "r"(dst), "l"(src) : "memory");
}
__device__ __forceinline__ void cp_commit() {
    asm volatile("cp.async.commit_group;" ::: "memory");
}
template <int N>
__device__ __forceinline__ void cp_wait() {
    asm volatile("cp.async.wait_group %0;" :: "n"(N) : "memory");
}

__device__ __forceinline__ void ldsm_x4(uint32_t* r, uint32_t addr) {
    asm volatile("ldmatrix.sync.aligned.m8n8.x4.shared.b16 {%0,%1,%2,%3}, [%4];"
                 : "=r"(r[0]), "=r"(r[1]), "=r"(r[2]), "=r"(r[3]) : "r"(addr));
}

__device__ __forceinline__ void mma16816(float* c, const uint32_t* a, const uint32_t* b) {
    asm volatile(
        "mma.sync.aligned.m16n8k16.row.col.f32.f16.f16.f32 "
        "{%0,%1,%2,%3}, {%4,%5,%6,%7}, {%8,%9}, {%0,%1,%2,%3};"
        : "+f"(c[0]), "+f"(c[1]), "+f"(c[2]), "+f"(c[3])
        : "r"(a[0]), "r"(a[1]), "r"(a[2]), "r"(a[3]), "r"(b[0]), "r"(b[1]));
}

// swizzled byte offset within a [rows][64] fp16 tile (128B rows)
__device__ __forceinline__ uint32_t swz(int r, int kb) {
    return (uint32_t)(r * 128 + (kb ^ ((r & 7) << 4)));
}

// ---------------------------------------------------------------------------
// Prep kernels
// ---------------------------------------------------------------------------
__global__ void k_convert_x(const float4* __restrict__ x) {
    size_t i = (size_t)blockIdx.x * blockDim.x + threadIdx.x;   // float4s
    float4 v = x[i];
    union { __half2 h2[2]; uint2 u; } o;
    o.h2[0] = __float22half2_rn(make_float2(v.x, v.y));
    o.h2[1] = __float22half2_rn(make_float2(v.z, v.w));
    *reinterpret_cast<uint2*>(g_A + i * 4) = o.u;
}

// detect weight_packed storage: uint8-packed words vs int32-expanded bytes
__global__ void k_detect(const uint32_t* __restrict__ wp) {
    if (blockIdx.x == 0 && threadIdx.x == 0) {
        int expanded = 1;
        #pragma unroll 1
        for (int i = 0; i < 64; i++)
            if (wp[i] & 0xFFFFFF00u) { expanded = 0; break; }
        g_wfmt = expanded;
    }
}

// one thread <-> 8 logical packed bytes = 16 weights = 16 output halfs
__global__ void k_dequant(const uint32_t* __restrict__ wp,
                          const float* __restrict__ cent,
                          const float* __restrict__ scales) {
    __shared__ float sc[16];
    if (threadIdx.x < 16) sc[threadIdx.x] = cent[threadIdx.x];
    __syncthreads();

    const int t  = blockIdx.x * blockDim.x + threadIdx.x;  // 8-byte group idx
    const int o  = t >> 8;             // 256 groups per output row (2048 B/row)
    const int jb = (t & 255) * 8;      // byte offset within row
    const float s = __ldg(scales + o * 64 + (jb >> 5));    // 32 bytes per block

    uint32_t w[2];
    if (g_wfmt) {                      // int32-expanded: one byte per int32
        const int32_t* wi = reinterpret_cast<const int32_t*>(wp);
        const size_t j0 = (size_t)t * 8;
        w[0] = w[1] = 0;
        #pragma unroll
        for (int i = 0; i < 4; i++) {
            w[0] |= ((uint32_t)wi[j0 + i]     & 0xFFu) << (8 * i);
            w[1] |= ((uint32_t)wi[j0 + 4 + i] & 0xFFu) << (8 * i);
        }
    } else {                           // true uint8 packing: read as words
        w[0] = wp[t * 2];
        w[1] = wp[t * 2 + 1];
    }

    union { __half h[16]; uint4 u[2]; } out;
    #pragma unroll
    for (int half = 0; half < 2; half++) {
        const uint32_t word = w[half];
        #pragma unroll
        for (int b = 0; b < 4; b++) {
            const uint32_t byte = (word >> (8 * b)) & 0xFF;
            const int base = half * 8 + 2 * b;
            out.h[base + 0] = __float2half(sc[byte >> 4] * s);   // HIGH nibble first
            out.h[base + 1] = __float2half(sc[byte & 15] * s);
        }
    }
    uint4* dst = reinterpret_cast<uint4*>(g_B + (size_t)o * KDIM + (size_t)jb * 2);
    dst[0] = out.u[0];
    dst[1] = out.u[1];
}

// ---------------------------------------------------------------------------
// GEMM: out[8192,4096] = A[8192,4096] @ B[4096,4096]^T  (fp16 in, fp32 acc)
// ---------------------------------------------------------------------------
__global__ void __launch_bounds__(256, 2) k_gemm(float* __restrict__ out) {
    extern __shared__ char smem[];
    const uint32_t sbase = smem_u32(smem);

    const int tid  = threadIdx.x;
    const int wid  = tid >> 5;
    const int lane = tid & 31;
    const int m0   = blockIdx.y * TM;
    const int n0   = blockIdx.x * TN;

    const int wm0 = (wid >> 2) * 64;    // warp m offset
    const int wn0 = (wid & 3) * 32;     // warp n offset

    float acc[4][4][4];
    #pragma unroll
    for (int i = 0; i < 4; i++)
        #pragma unroll
        for (int j = 0; j < 4; j++)
            #pragma unroll
            for (int k = 0; k < 4; k++) acc[i][j][k] = 0.f;

    auto issue_chunk = [&](int kc, int stage) {
        const uint32_t aS = sbase + stage * STAGE_BYTES;
        const uint32_t bS = aS + TM * 128;
        const size_t kofs = (size_t)kc * TK;
        #pragma unroll
        for (int it = 0; it < 8; it++) {
            const int v = tid + it * 256;
            if (it < 4) {
                const int r = v >> 3, c = v & 7;
                cp_async16(aS + swz(r, c * 16),
                           g_A + (size_t)(m0 + r) * KDIM + kofs + c * 8);
            } else {
                const int t = v - 1024;
                const int r = t >> 3, c = t & 7;
                cp_async16(bS + swz(r, c * 16),
                           g_B + (size_t)(n0 + r) * KDIM + kofs + c * 8);
            }
        }
        cp_commit();
    };

    issue_chunk(0, 0);
    issue_chunk(1, 1);

    const int laneA_r  = lane & 15;
    const int laneA_kb = (lane >> 4) << 4;
    const int laneB_r  = ((lane & 16) >> 1) + (lane & 7);
    const int laneB_kb = ((lane >> 3) & 1) << 4;

    for (int kc = 0; kc < NCHUNK; kc++) {
        const int stage = kc % STAGES;

        // chunk kc resident (committed groups = kc+2, pending <= 1)
        cp_wait<1>();
        __syncthreads();

        // refill the stage all warps finished reading in iteration kc-1
        if (kc + 2 < NCHUNK) issue_chunk(kc + 2, (kc + 2) % STAGES);
        else cp_commit();   // empty group keeps wait<1> accounting exact

        const uint32_t aS = sbase + stage * STAGE_BYTES;
        const uint32_t bS = aS + TM * 128;

        #pragma unroll
        for (int ks = 0; ks < 4; ks++) {
            const int kb = ks * 32;
            uint32_t a[4][4];
            #pragma unroll
            for (int tm = 0; tm < 4; tm++) {
                const int r = wm0 + tm * 16 + laneA_r;
                ldsm_x4(a[tm], aS + swz(r, kb + laneA_kb));
            }
            uint32_t b[4][2];
            #pragma unroll
            for (int j = 0; j < 2; j++) {
                const int r = wn0 + j * 16 + laneB_r;
                uint32_t t[4];
                ldsm_x4(t, bS + swz(r, kb + laneB_kb));
                b[2*j][0] = t[0];   b[2*j][1] = t[1];
                b[2*j+1][0] = t[2]; b[2*j+1][1] = t[3];
            }
            #pragma unroll
            for (int tm = 0; tm < 4; tm++)
                #pragma unroll
                for (int tn = 0; tn < 4; tn++)
                    mma16816(acc[tm][tn], a[tm], b[tn]);
        }
    }

    const int mrow = lane >> 2;
    const int ncol = (lane & 3) * 2;
    #pragma unroll
    for (int tm = 0; tm < 4; tm++) {
        #pragma unroll
        for (int tn = 0; tn < 4; tn++) {
            const int m = m0 + wm0 + tm * 16 + mrow;
            const int n = n0 + wn0 + tn * 8 + ncol;
            float2* p0 = reinterpret_cast<float2*>(out + (size_t)m * ODIM + n);
            float2* p1 = reinterpret_cast<float2*>(out + (size_t)(m + 8) * ODIM + n);
            *p0 = make_float2(acc[tm][tn][0], acc[tm][tn][1]);
            *p1 = make_float2(acc[tm][tn][2], acc[tm][tn][3]);
        }
    }
}

// ---------------------------------------------------------------------------
extern "C" void kernel_launch(void* const* d_in, const int* in_sizes, int n_in,
                              void* d_out, int out_size) {
    (void)out_size;
    const float*    x      = nullptr;
    const uint32_t* wp     = nullptr;
    const float*    cent   = nullptr;
    const float*    scales = nullptr;

    for (int i = 0; i < n_in; i++) {
        switch (in_sizes[i]) {
            case 16:        cent   = (const float*)d_in[i];    break;
            case 262144:    scales = (const float*)d_in[i];    break;
            case 33554432:  x      = (const float*)d_in[i];    break;
            default:        wp     = (const uint32_t*)d_in[i]; break;  // 8388608
        }
    }
    float* outp = (float*)d_out;

    k_detect<<<1, 32>>>(wp);
    k_convert_x<<<32768, 256>>>(reinterpret_cast<const float4*>(x));
    k_dequant<<<4096, 256>>>(wp, cent, scales);   // 1,048,576 threads

    cudaFuncSetAttribute(k_gemm, cudaFuncAttributeMaxDynamicSharedMemorySize, SMEM_BYTES);
    k_gemm<<<dim3(ODIM / TN, MDIM / TM), 256, SMEM_BYTES>>>(outp);
}